// round 11
// baseline (speedup 1.0000x reference)
#include <cuda_runtime.h>
#include <cstddef>

// Problem constants
constexpr int T   = 50;
constexpr int B   = 512;
constexpr int IN  = 784;
constexpr int H   = 800;
constexpr int OUT = 10;
constexpr int MROWS = T * B;        // 25600
constexpr int BH    = B * H;        // 409600
constexpr int BO    = B * OUT;      // 5120

#define BETA 0.95f

// Scratch (static device globals; no runtime allocation)
__device__ float g_x1[(size_t)T * BH];   // x @ W1^T   (82 MB)
__device__ float g_z2[(size_t)T * BH];   // spk1 @ W2^T(82 MB)
__device__ float g_z3[(size_t)T * BO];   // spk2 @ W3^T(1 MB)

// ---------------------------------------------------------------------------
// Packed f32x2 primitives (sm_103a). ptxas never auto-fuses these — PTX only.
// Each op = one issue slot, two independent fp32 lanes.
// ---------------------------------------------------------------------------
typedef unsigned long long ull;

__device__ __forceinline__ ull PK2(float lo, float hi) {
    ull r; asm("mov.b64 %0, {%1, %2};" : "=l"(r) : "f"(lo), "f"(hi)); return r;
}
__device__ __forceinline__ void UPK2(ull v, float& lo, float& hi) {
    asm("mov.b64 {%0, %1}, %2;" : "=f"(lo), "=f"(hi) : "l"(v));
}
__device__ __forceinline__ ull ADD2(ull a, ull b) {
    ull r; asm("add.rn.f32x2 %0, %1, %2;" : "=l"(r) : "l"(a), "l"(b)); return r;
}
__device__ __forceinline__ ull MUL2(ull a, ull b) {
    ull r; asm("mul.rn.f32x2 %0, %1, %2;" : "=l"(r) : "l"(a), "l"(b)); return r;
}
__device__ __forceinline__ ull FMA2(ull a, ull b, ull c) {
    ull r; asm("fma.rn.f32x2 %0, %1, %2, %3;"
               : "=l"(r) : "l"(a), "l"(b), "l"(c)); return r;
}

// ---------------------------------------------------------------------------
// EXACT-DOT GEMM via compensated fp32 (Dot2), f32x2-packed across m-pairs.
// Per-lane op sequence is bit-identical to the scalar Dot2 kernel proven
// bit-exact vs the reference (R10: rel_err = 0):
//   TwoProd: p = a*b; ep = fma(a,b,-p)
//   TwoSum:  t = s+p; bb = t-s; err = (s-(t-bb)) + (p-bb); c += err + ep
// Subtraction x-y is implemented as fma(y,-1,x) — bitwise == __fsub_rn(x,y).
// BM=128, BN=80, BK=16, 256 threads, (4 m-pairs x 5 n) per thread.
// ---------------------------------------------------------------------------
__global__ void __launch_bounds__(256)
gemm_nt_df32(const float* __restrict__ A, const float* __restrict__ Bw,
             float* __restrict__ C, int M, int N, int K)
{
    __shared__ float As[16][130];   // 130: keeps float2 reads 8B-aligned
    __shared__ float Bs[16][81];

    const int tid = threadIdx.x;
    const int tx  = tid & 15;       // n direction
    const int ty  = tid >> 4;       // m direction
    const int m0  = blockIdx.x * 128;
    const int n0  = blockIdx.y * 80;

    const ull NEG1 = PK2(-1.f, -1.f);

    ull S[4][5], Cc[4][5];
#pragma unroll
    for (int i = 0; i < 4; i++)
#pragma unroll
        for (int j = 0; j < 5; j++) { S[i][j] = PK2(0.f, 0.f); Cc[i][j] = S[i][j]; }

    for (int k0 = 0; k0 < K; k0 += 16) {
#pragma unroll
        for (int j = tid; j < 512; j += 256) {
            int row = j >> 2;
            int c4  = (j & 3) << 2;
            float4 v = *reinterpret_cast<const float4*>(
                A + (size_t)(m0 + row) * K + k0 + c4);
            As[c4 + 0][row] = v.x;
            As[c4 + 1][row] = v.y;
            As[c4 + 2][row] = v.z;
            As[c4 + 3][row] = v.w;
        }
#pragma unroll
        for (int j = tid; j < 320; j += 256) {
            int row = j >> 2;
            int c4  = (j & 3) << 2;
            float4 v = *reinterpret_cast<const float4*>(
                Bw + (size_t)(n0 + row) * K + k0 + c4);
            Bs[c4 + 0][row] = v.x;
            Bs[c4 + 1][row] = v.y;
            Bs[c4 + 2][row] = v.z;
            Bs[c4 + 3][row] = v.w;
        }
        __syncthreads();

#pragma unroll
        for (int kk = 0; kk < 16; kk++) {
            ull a2[4], b2[5];
#pragma unroll
            for (int i = 0; i < 4; i++) {
                float2 av = *reinterpret_cast<const float2*>(
                    &As[kk][ty * 8 + i * 2]);
                a2[i] = PK2(av.x, av.y);
            }
#pragma unroll
            for (int j = 0; j < 5; j++) {
                const float bv = Bs[kk][tx * 5 + j];
                b2[j] = PK2(bv, bv);
            }
#pragma unroll
            for (int i = 0; i < 4; i++)
#pragma unroll
                for (int j = 0; j < 5; j++) {
                    const ull p   = MUL2(a2[i], b2[j]);
                    const ull np  = MUL2(p, NEG1);
                    const ull ep  = FMA2(a2[i], b2[j], np);    // exact prod err
                    const ull t   = ADD2(S[i][j], p);
                    const ull bb  = FMA2(S[i][j], NEG1, t);    // t - s
                    const ull tmb = FMA2(bb, NEG1, t);         // t - bb
                    const ull e1  = FMA2(tmb, NEG1, S[i][j]);  // s - (t-bb)
                    const ull e2  = FMA2(bb, NEG1, p);         // p - bb
                    S[i][j]  = t;
                    Cc[i][j] = ADD2(Cc[i][j], ADD2(ADD2(e1, e2), ep));
                }
        }
        __syncthreads();
    }

#pragma unroll
    for (int i = 0; i < 4; i++) {
#pragma unroll
        for (int j = 0; j < 5; j++) {
            const ull o = ADD2(S[i][j], Cc[i][j]);
            float lo, hi; UPK2(o, lo, hi);
            const int r  = m0 + ty * 8 + i * 2;
            const int cc = n0 + tx * 5 + j;
            C[(size_t)r * N + cc]       = lo;
            C[(size_t)(r + 1) * N + cc] = hi;
        }
    }
}

// ---------------------------------------------------------------------------
// SERIAL-FP32 GEMM (layer 2), f32x2-packed across m-pairs.
// Per output: strict ascending-k fp32 FMA chain from 0 — bit-identical to
// the scalar version proven exact in R9/R10 (lanes are independent outputs).
// ---------------------------------------------------------------------------
__global__ void __launch_bounds__(256)
gemm_nt_f32(const float* __restrict__ A, const float* __restrict__ Bw,
            float* __restrict__ C, int M, int N, int K)
{
    __shared__ float As[16][130];
    __shared__ float Bs[16][81];

    const int tid = threadIdx.x;
    const int tx  = tid & 15;
    const int ty  = tid >> 4;
    const int m0  = blockIdx.x * 128;
    const int n0  = blockIdx.y * 80;

    ull acc[4][5];
#pragma unroll
    for (int i = 0; i < 4; i++)
#pragma unroll
        for (int j = 0; j < 5; j++) acc[i][j] = PK2(0.f, 0.f);

    for (int k0 = 0; k0 < K; k0 += 16) {
#pragma unroll
        for (int j = tid; j < 512; j += 256) {
            int row = j >> 2;
            int c4  = (j & 3) << 2;
            float4 v = *reinterpret_cast<const float4*>(
                A + (size_t)(m0 + row) * K + k0 + c4);
            As[c4 + 0][row] = v.x;
            As[c4 + 1][row] = v.y;
            As[c4 + 2][row] = v.z;
            As[c4 + 3][row] = v.w;
        }
#pragma unroll
        for (int j = tid; j < 320; j += 256) {
            int row = j >> 2;
            int c4  = (j & 3) << 2;
            float4 v = *reinterpret_cast<const float4*>(
                Bw + (size_t)(n0 + row) * K + k0 + c4);
            Bs[c4 + 0][row] = v.x;
            Bs[c4 + 1][row] = v.y;
            Bs[c4 + 2][row] = v.z;
            Bs[c4 + 3][row] = v.w;
        }
        __syncthreads();

#pragma unroll
        for (int kk = 0; kk < 16; kk++) {   // strict ascending-k chain per lane
            ull a2[4], b2[5];
#pragma unroll
            for (int i = 0; i < 4; i++) {
                float2 av = *reinterpret_cast<const float2*>(
                    &As[kk][ty * 8 + i * 2]);
                a2[i] = PK2(av.x, av.y);
            }
#pragma unroll
            for (int j = 0; j < 5; j++) {
                const float bv = Bs[kk][tx * 5 + j];
                b2[j] = PK2(bv, bv);
            }
#pragma unroll
            for (int i = 0; i < 4; i++)
#pragma unroll
                for (int j = 0; j < 5; j++)
                    acc[i][j] = FMA2(a2[i], b2[j], acc[i][j]);
        }
        __syncthreads();
    }

#pragma unroll
    for (int i = 0; i < 4; i++) {
#pragma unroll
        for (int j = 0; j < 5; j++) {
            float lo, hi; UPK2(acc[i][j], lo, hi);
            const int r  = m0 + ty * 8 + i * 2;
            const int cc = n0 + tx * 5 + j;
            C[(size_t)r * N + cc]       = lo;
            C[(size_t)(r + 1) * N + cc] = hi;
        }
    }
}

// ---------------------------------------------------------------------------
// Skinny exact-dot GEMM (layer 3): f64 accumulate — proven exact, ~0.1 ms.
// ---------------------------------------------------------------------------
__global__ void __launch_bounds__(640)
gemm3_f64(const float* __restrict__ A, const float* __restrict__ W3,
          float* __restrict__ Cz)
{
    __shared__ float As[64][81];
    const int tid  = threadIdx.x;
    const int r    = tid & 63;
    const int o    = tid >> 6;          // 0..9
    const int row0 = blockIdx.x * 64;

    double acc = 0.0;
    for (int k0 = 0; k0 < 800; k0 += 80) {
        for (int j = tid; j < 1280; j += 640) {
            int rr = j / 20;
            int c  = (j % 20) * 4;
            float4 v = *reinterpret_cast<const float4*>(
                A + (size_t)(row0 + rr) * 800 + k0 + c);
            As[rr][c + 0] = v.x;
            As[rr][c + 1] = v.y;
            As[rr][c + 2] = v.z;
            As[rr][c + 3] = v.w;
        }
        __syncthreads();
        const float* w = W3 + (size_t)o * 800 + k0;
#pragma unroll
        for (int k = 0; k < 80; k++)
            acc = fma((double)As[r][k], (double)__ldg(w + k), acc);
        __syncthreads();
    }
    Cz[(size_t)(row0 + r) * OUT + o] = (float)acc;
}

// ---------------------------------------------------------------------------
// LIF scans — EXACT associations proven in R9/R10 (rel_err = 0). Do not change.
// ORDER==1 (layer 1): xt = round(z + b1); m = round(round(BETA*m) + xt)
// ORDER==2 (layer 2): m = round(round(round(BETA*m) + z) + b)
// ---------------------------------------------------------------------------
template <int ORDER>
__global__ void __launch_bounds__(256)
scan_hidden(const float* __restrict__ z, const float* __restrict__ bias,
            const float* __restrict__ thr, float* __restrict__ spk_out)
{
    const int idx = blockIdx.x * blockDim.x + threadIdx.x;
    if (idx >= BH) return;
    const int h = idx % H;
    const float bv = bias[h];
    const float tv = thr[h];
    float m = 0.f;
#pragma unroll
    for (int t = 0; t < T; t++) {
        const float zv = z[(size_t)t * BH + idx];
        float mnew;
        if (ORDER == 1) {
            const float xt = __fadd_rn(zv, bv);
            mnew = __fadd_rn(__fmul_rn(BETA, m), xt);
        } else {
            mnew = __fadd_rn(__fadd_rn(__fmul_rn(BETA, m), zv), bv);
        }
        const bool fire = (mnew > tv);
        spk_out[(size_t)t * BH + idx] = fire ? 1.f : 0.f;
        m = fire ? 0.f : mnew;
    }
}

__global__ void __launch_bounds__(256)
scan_out(const float* __restrict__ z3, const float* __restrict__ b3,
         float* __restrict__ s3, float* __restrict__ sum_out)
{
    const int idx = blockIdx.x * blockDim.x + threadIdx.x;
    if (idx >= BO) return;
    const int o = idx % OUT;
    const float bv = b3[o];
    float m = 0.f, sum = 0.f;
#pragma unroll
    for (int t = 0; t < T; t++) {
        const float zv = z3[(size_t)t * BO + idx];
        const float mnew = __fadd_rn(__fadd_rn(__fmul_rn(BETA, m), zv), bv);
        const bool fire = (mnew > 1.0f);
        const float s = fire ? 1.f : 0.f;
        s3[(size_t)t * BO + idx] = s;
        sum = __fadd_rn(sum, s);
        m = fire ? 0.f : mnew;
    }
    sum_out[idx] = sum;
}

// ---------------------------------------------------------------------------
// kernel_launch — 6 graph-capturable launches, allocation-free.
// Inputs: x, W1, b1, W2, b2, W3, b3, thresh1, thresh2
// Outputs: sum[512,10], s1r[50,512,800], s2r[50,512,800], s3r[50,512,10]
// ---------------------------------------------------------------------------
extern "C" void kernel_launch(void* const* d_in, const int* in_sizes, int n_in,
                              void* d_out, int out_size)
{
    const float* x    = (const float*)d_in[0];
    const float* W1   = (const float*)d_in[1];
    const float* b1   = (const float*)d_in[2];
    const float* W2   = (const float*)d_in[3];
    const float* b2   = (const float*)d_in[4];
    const float* W3   = (const float*)d_in[5];
    const float* b3   = (const float*)d_in[6];
    const float* thr1 = (const float*)d_in[7];
    const float* thr2 = (const float*)d_in[8];

    float* out     = (float*)d_out;
    float* out_sum = out;                                  // [512,10]
    float* s1      = out + (size_t)BO;                     // [50,512,800]
    float* s2      = s1 + (size_t)T * BH;                  // [50,512,800]
    float* s3      = s2 + (size_t)T * BH;                  // [50,512,10]

    void *px1, *pz2, *pz3;
    cudaGetSymbolAddress(&px1, g_x1);
    cudaGetSymbolAddress(&pz2, g_z2);
    cudaGetSymbolAddress(&pz3, g_z3);

    // 1) x1 = exact-dot(x, W1^T) — packed compensated fp32
    {
        dim3 grid(MROWS / 128, H / 80);
        gemm_nt_df32<<<grid, 256>>>(x, W1, (float*)px1, MROWS, H, IN);
    }
    // 2) layer-1 LIF scan -> spk1  [bit-exact]
    scan_hidden<1><<<(BH + 255) / 256, 256>>>((const float*)px1, b1, thr1, s1);

    // 3) z2 = serial-fp32(spk1 @ W2^T) — packed, chain order preserved
    {
        dim3 grid(MROWS / 128, H / 80);
        gemm_nt_f32<<<grid, 256>>>(s1, W2, (float*)pz2, MROWS, H, H);
    }
    // 4) layer-2 LIF scan -> spk2  [bit-exact]
    scan_hidden<2><<<(BH + 255) / 256, 256>>>((const float*)pz2, b2, thr2, s2);

    // 5) z3 = exact-dot(spk2, W3^T)  [bit-exact]
    gemm3_f64<<<MROWS / 64, 640>>>(s2, W3, (float*)pz3);

    // 6) layer-3 LIF scan -> s3r + spike-count sum
    scan_out<<<(BO + 255) / 256, 256>>>((const float*)pz3, b3, s3, out_sum);
}

// round 12
// speedup vs baseline: 1.1947x; 1.1947x over previous
#include <cuda_runtime.h>
#include <cstddef>

// Problem constants
constexpr int T   = 50;
constexpr int B   = 512;
constexpr int IN  = 784;
constexpr int H   = 800;
constexpr int OUT = 10;
constexpr int MROWS = T * B;        // 25600
constexpr int BH    = B * H;        // 409600
constexpr int BO    = B * OUT;      // 5120

#define BETA 0.95f

// Scratch (static device globals; no runtime allocation)
__device__ float g_x1[(size_t)T * BH];   // x @ W1^T   (82 MB)
__device__ float g_z2[(size_t)T * BH];   // spk1 @ W2^T(82 MB)
__device__ float g_z3[(size_t)T * BO];   // spk2 @ W3^T(1 MB)

// ---------------------------------------------------------------------------
// EXACT-DOT GEMM via compensated fp32 (Dot2) — scalar form, PROVEN bit-exact
// vs reference through all downstream spike comparisons (R10: rel_err = 0).
//   TwoProd: p = a*b; ep = fma(a,b,-p)
//   TwoSum:  t = s+p; bb = t-s; err = (s-(t-bb)) + (p-bb); c += err + ep
// BM=128, BN=80, BK=16, 256 threads, 8x5 micro-tile. Compute-bound at
// ~10 fma-pipe ops per MAC; LDS traffic negligible at this op intensity.
// ---------------------------------------------------------------------------
__global__ void __launch_bounds__(256)
gemm_nt_df32(const float* __restrict__ A, const float* __restrict__ Bw,
             float* __restrict__ C, int M, int N, int K)
{
    __shared__ float As[16][129];
    __shared__ float Bs[16][81];

    const int tid = threadIdx.x;
    const int tx  = tid & 15;       // n direction
    const int ty  = tid >> 4;       // m direction
    const int m0  = blockIdx.x * 128;
    const int n0  = blockIdx.y * 80;

    float s[8][5], c[8][5];
#pragma unroll
    for (int i = 0; i < 8; i++)
#pragma unroll
        for (int j = 0; j < 5; j++) { s[i][j] = 0.f; c[i][j] = 0.f; }

    for (int k0 = 0; k0 < K; k0 += 16) {
#pragma unroll
        for (int j = tid; j < 512; j += 256) {
            int row = j >> 2;
            int c4  = (j & 3) << 2;
            float4 v = *reinterpret_cast<const float4*>(
                A + (size_t)(m0 + row) * K + k0 + c4);
            As[c4 + 0][row] = v.x;
            As[c4 + 1][row] = v.y;
            As[c4 + 2][row] = v.z;
            As[c4 + 3][row] = v.w;
        }
#pragma unroll
        for (int j = tid; j < 320; j += 256) {
            int row = j >> 2;
            int c4  = (j & 3) << 2;
            float4 v = *reinterpret_cast<const float4*>(
                Bw + (size_t)(n0 + row) * K + k0 + c4);
            Bs[c4 + 0][row] = v.x;
            Bs[c4 + 1][row] = v.y;
            Bs[c4 + 2][row] = v.z;
            Bs[c4 + 3][row] = v.w;
        }
        __syncthreads();

#pragma unroll
        for (int kk = 0; kk < 16; kk++) {
            float a[8], b[5];
#pragma unroll
            for (int i = 0; i < 8; i++) a[i] = As[kk][ty * 8 + i];
#pragma unroll
            for (int j = 0; j < 5; j++) b[j] = Bs[kk][tx * 5 + j];
#pragma unroll
            for (int i = 0; i < 8; i++)
#pragma unroll
                for (int j = 0; j < 5; j++) {
                    const float p  = __fmul_rn(a[i], b[j]);
                    const float ep = __fmaf_rn(a[i], b[j], -p);
                    const float t   = __fadd_rn(s[i][j], p);
                    const float bb  = __fsub_rn(t, s[i][j]);
                    const float err = __fadd_rn(
                        __fsub_rn(s[i][j], __fsub_rn(t, bb)),
                        __fsub_rn(p, bb));
                    s[i][j] = t;
                    c[i][j] = __fadd_rn(c[i][j], __fadd_rn(err, ep));
                }
        }
        __syncthreads();
    }

#pragma unroll
    for (int i = 0; i < 8; i++) {
        const int r = m0 + ty * 8 + i;
#pragma unroll
        for (int j = 0; j < 5; j++)
            C[(size_t)r * N + n0 + tx * 5 + j] =
                __fadd_rn(s[i][j], c[i][j]);
    }
}

// ---------------------------------------------------------------------------
// SERIAL-FP32 GEMM (layer 2) — strict ascending-k fp32 FMA chain from 0 per
// output (bit-exact class, proven R9/R10). Widened to 8x10 micro-tile
// (BM=128, BN=160) so LDS words per FMA drops below the 32 words/cyc
// crossbar: 18 words / 80 FMA -> 28.8 words/cyc at full rate (was 41.6).
// ---------------------------------------------------------------------------
__global__ void __launch_bounds__(256)
gemm_nt_f32(const float* __restrict__ A, const float* __restrict__ Bw,
            float* __restrict__ C, int M, int N, int K)
{
    __shared__ float As[16][129];
    __shared__ float Bs[16][161];

    const int tid = threadIdx.x;
    const int tx  = tid & 15;       // n direction (x10)
    const int ty  = tid >> 4;       // m direction (x8)
    const int m0  = blockIdx.x * 128;
    const int n0  = blockIdx.y * 160;

    float acc[8][10];
#pragma unroll
    for (int i = 0; i < 8; i++)
#pragma unroll
        for (int j = 0; j < 10; j++) acc[i][j] = 0.f;

    for (int k0 = 0; k0 < K; k0 += 16) {
        // A tile: 128 rows x 16 k = 512 float4
#pragma unroll
        for (int j = tid; j < 512; j += 256) {
            int row = j >> 2;
            int c4  = (j & 3) << 2;
            float4 v = *reinterpret_cast<const float4*>(
                A + (size_t)(m0 + row) * K + k0 + c4);
            As[c4 + 0][row] = v.x;
            As[c4 + 1][row] = v.y;
            As[c4 + 2][row] = v.z;
            As[c4 + 3][row] = v.w;
        }
        // B tile: 160 rows x 16 k = 640 float4
#pragma unroll
        for (int j = tid; j < 640; j += 256) {
            int row = j >> 2;
            int c4  = (j & 3) << 2;
            float4 v = *reinterpret_cast<const float4*>(
                Bw + (size_t)(n0 + row) * K + k0 + c4);
            Bs[c4 + 0][row] = v.x;
            Bs[c4 + 1][row] = v.y;
            Bs[c4 + 2][row] = v.z;
            Bs[c4 + 3][row] = v.w;
        }
        __syncthreads();

#pragma unroll
        for (int kk = 0; kk < 16; kk++) {   // strict ascending-k chain
            float a[8], b[10];
#pragma unroll
            for (int i = 0; i < 8; i++) a[i] = As[kk][ty * 8 + i];
#pragma unroll
            for (int j = 0; j < 10; j++) b[j] = Bs[kk][tx * 10 + j];
#pragma unroll
            for (int i = 0; i < 8; i++)
#pragma unroll
                for (int j = 0; j < 10; j++)
                    acc[i][j] = fmaf(a[i], b[j], acc[i][j]);
        }
        __syncthreads();
    }

#pragma unroll
    for (int i = 0; i < 8; i++) {
        const int r = m0 + ty * 8 + i;
#pragma unroll
        for (int j = 0; j < 10; j++)
            C[(size_t)r * N + n0 + tx * 10 + j] = acc[i][j];
    }
}

// ---------------------------------------------------------------------------
// Skinny exact-dot GEMM (layer 3) via fp32 Dot2 (same accuracy class as the
// previous f64 version; ~8x cheaper than DFMA path).
// ---------------------------------------------------------------------------
__global__ void __launch_bounds__(640)
gemm3_df32(const float* __restrict__ A, const float* __restrict__ W3,
           float* __restrict__ Cz)
{
    __shared__ float As[64][81];
    const int tid  = threadIdx.x;
    const int r    = tid & 63;
    const int o    = tid >> 6;          // 0..9
    const int row0 = blockIdx.x * 64;

    float s = 0.f, c = 0.f;
    for (int k0 = 0; k0 < 800; k0 += 80) {
        for (int j = tid; j < 1280; j += 640) {
            int rr = j / 20;
            int cc = (j % 20) * 4;
            float4 v = *reinterpret_cast<const float4*>(
                A + (size_t)(row0 + rr) * 800 + k0 + cc);
            As[rr][cc + 0] = v.x;
            As[rr][cc + 1] = v.y;
            As[rr][cc + 2] = v.z;
            As[rr][cc + 3] = v.w;
        }
        __syncthreads();
        const float* w = W3 + (size_t)o * 800 + k0;
#pragma unroll
        for (int k = 0; k < 80; k++) {
            const float a = As[r][k];
            const float b = __ldg(w + k);
            const float p  = __fmul_rn(a, b);
            const float ep = __fmaf_rn(a, b, -p);
            const float t   = __fadd_rn(s, p);
            const float bb  = __fsub_rn(t, s);
            const float err = __fadd_rn(
                __fsub_rn(s, __fsub_rn(t, bb)),
                __fsub_rn(p, bb));
            s = t;
            c = __fadd_rn(c, __fadd_rn(err, ep));
        }
        __syncthreads();
    }
    Cz[(size_t)(row0 + r) * OUT + o] = __fadd_rn(s, c);
}

// ---------------------------------------------------------------------------
// LIF scans — EXACT associations proven in R9/R10 (rel_err = 0). Do not change.
// ORDER==1 (layer 1): xt = round(z + b1); m = round(round(BETA*m) + xt)
// ORDER==2 (layer 2): m = round(round(round(BETA*m) + z) + b)
// ---------------------------------------------------------------------------
template <int ORDER>
__global__ void __launch_bounds__(256)
scan_hidden(const float* __restrict__ z, const float* __restrict__ bias,
            const float* __restrict__ thr, float* __restrict__ spk_out)
{
    const int idx = blockIdx.x * blockDim.x + threadIdx.x;
    if (idx >= BH) return;
    const int h = idx % H;
    const float bv = bias[h];
    const float tv = thr[h];
    float m = 0.f;
#pragma unroll
    for (int t = 0; t < T; t++) {
        const float zv = z[(size_t)t * BH + idx];
        float mnew;
        if (ORDER == 1) {
            const float xt = __fadd_rn(zv, bv);
            mnew = __fadd_rn(__fmul_rn(BETA, m), xt);
        } else {
            mnew = __fadd_rn(__fadd_rn(__fmul_rn(BETA, m), zv), bv);
        }
        const bool fire = (mnew > tv);
        spk_out[(size_t)t * BH + idx] = fire ? 1.f : 0.f;
        m = fire ? 0.f : mnew;
    }
}

__global__ void __launch_bounds__(256)
scan_out(const float* __restrict__ z3, const float* __restrict__ b3,
         float* __restrict__ s3, float* __restrict__ sum_out)
{
    const int idx = blockIdx.x * blockDim.x + threadIdx.x;
    if (idx >= BO) return;
    const int o = idx % OUT;
    const float bv = b3[o];
    float m = 0.f, sum = 0.f;
#pragma unroll
    for (int t = 0; t < T; t++) {
        const float zv = z3[(size_t)t * BO + idx];
        const float mnew = __fadd_rn(__fadd_rn(__fmul_rn(BETA, m), zv), bv);
        const bool fire = (mnew > 1.0f);
        const float s = fire ? 1.f : 0.f;
        s3[(size_t)t * BO + idx] = s;
        sum = __fadd_rn(sum, s);
        m = fire ? 0.f : mnew;
    }
    sum_out[idx] = sum;
}

// ---------------------------------------------------------------------------
// kernel_launch — 6 graph-capturable launches, allocation-free.
// Inputs: x, W1, b1, W2, b2, W3, b3, thresh1, thresh2
// Outputs: sum[512,10], s1r[50,512,800], s2r[50,512,800], s3r[50,512,10]
// ---------------------------------------------------------------------------
extern "C" void kernel_launch(void* const* d_in, const int* in_sizes, int n_in,
                              void* d_out, int out_size)
{
    const float* x    = (const float*)d_in[0];
    const float* W1   = (const float*)d_in[1];
    const float* b1   = (const float*)d_in[2];
    const float* W2   = (const float*)d_in[3];
    const float* b2   = (const float*)d_in[4];
    const float* W3   = (const float*)d_in[5];
    const float* b3   = (const float*)d_in[6];
    const float* thr1 = (const float*)d_in[7];
    const float* thr2 = (const float*)d_in[8];

    float* out     = (float*)d_out;
    float* out_sum = out;                                  // [512,10]
    float* s1      = out + (size_t)BO;                     // [50,512,800]
    float* s2      = s1 + (size_t)T * BH;                  // [50,512,800]
    float* s3      = s2 + (size_t)T * BH;                  // [50,512,10]

    void *px1, *pz2, *pz3;
    cudaGetSymbolAddress(&px1, g_x1);
    cudaGetSymbolAddress(&pz2, g_z2);
    cudaGetSymbolAddress(&pz3, g_z3);

    // 1) x1 = exact-dot(x, W1^T) — scalar compensated fp32 (R10-proven)
    {
        dim3 grid(MROWS / 128, H / 80);
        gemm_nt_df32<<<grid, 256>>>(x, W1, (float*)px1, MROWS, H, IN);
    }
    // 2) layer-1 LIF scan -> spk1  [bit-exact]
    scan_hidden<1><<<(BH + 255) / 256, 256>>>((const float*)px1, b1, thr1, s1);

    // 3) z2 = serial-fp32(spk1 @ W2^T) — wide tile, chain order preserved
    {
        dim3 grid(MROWS / 128, H / 160);
        gemm_nt_f32<<<grid, 256>>>(s1, W2, (float*)pz2, MROWS, H, H);
    }
    // 4) layer-2 LIF scan -> spk2  [bit-exact]
    scan_hidden<2><<<(BH + 255) / 256, 256>>>((const float*)pz2, b2, thr2, s2);

    // 5) z3 = exact-dot(spk2, W3^T) — fp32 Dot2 (was f64; ~8x cheaper)
    gemm3_df32<<<MROWS / 64, 640>>>(s2, W3, (float*)pz3);

    // 6) layer-3 LIF scan -> s3r + spike-count sum
    scan_out<<<(BO + 255) / 256, 256>>>((const float*)pz3, b3, s3, out_sum);
}